// round 15
// baseline (speedup 1.0000x reference)
#include <cuda_runtime.h>
#include <cuda_bf16.h>

#define F 128
#define CAP_N 51200
#define CAP_E 650000

__device__ float4 g_agg4[(size_t)CAP_N * (F / 4)];  // normalized agg rows
__device__ int    g_cnt[CAP_N];
__device__ int    g_rowptr[CAP_N + 1];
__device__ int    g_esrc[CAP_E];
__device__ float  g_ewt[CAP_E];

// ---------------------------------------------------------------------------
// CSR build (validated in R13)
// ---------------------------------------------------------------------------
__global__ void k_zero_cnt(int N) {
    int i = blockIdx.x * blockDim.x + threadIdx.x;
    if (i < N) g_cnt[i] = 0;
}

__global__ void k_count(const int* __restrict__ ei, int E, int N) {
    int e = blockIdx.x * blockDim.x + threadIdx.x;
    if (e >= E) return;
    int t = ei[E + e];
    if ((unsigned)t < (unsigned)N) atomicAdd(&g_cnt[t], 1);
}

#define SCAN_T 1024
__global__ __launch_bounds__(SCAN_T, 1)
void k_scan(int N) {
    __shared__ int part[SCAN_T];
    int tid = threadIdx.x;
    int per = (N + SCAN_T - 1) / SCAN_T;
    int b = tid * per;
    int e = b + per; if (e > N) e = N; if (b > N) b = N;
    int s = 0;
    for (int i = b; i < e; ++i) s += g_cnt[i];
    part[tid] = s;
    __syncthreads();
    for (int off = 1; off < SCAN_T; off <<= 1) {
        int v = (tid >= off) ? part[tid - off] : 0;
        __syncthreads();
        part[tid] += v;
        __syncthreads();
    }
    int run = tid ? part[tid - 1] : 0;
    for (int i = b; i < e; ++i) {
        g_rowptr[i] = run;
        run += g_cnt[i];
        g_cnt[i] = 0;           // reset for fill cursor
    }
    if (tid == SCAN_T - 1) g_rowptr[N] = run;
}

__global__ void k_fill(const int* __restrict__ ei,
                       const float* __restrict__ w, int E, int N) {
    int e = blockIdx.x * blockDim.x + threadIdx.x;
    if (e >= E) return;
    int s = ei[e];
    int t = ei[E + e];
    if ((unsigned)s >= (unsigned)N || (unsigned)t >= (unsigned)N) return;
    int pos = g_rowptr[t] + atomicAdd(&g_cnt[t], 1);
    g_esrc[pos] = s;
    g_ewt[pos] = expf(w[e]);
}

// ---------------------------------------------------------------------------
// warp-per-node aggregation with explicit MLP (8/4-batched gathers):
// S = sum(ew * x[src]); write S/(||S|| + dsum*1e-9)  (softmax-div + L2 fold)
// ---------------------------------------------------------------------------
__global__ void k_aggregate(const float* __restrict__ x, int N) {
    int gw = (blockIdx.x * blockDim.x + threadIdx.x) >> 5;
    int lane = threadIdx.x & 31;
    if (gw >= N) return;
    int beg = g_rowptr[gw], end = g_rowptr[gw + 1];

    float4 acc = make_float4(0.f, 0.f, 0.f, 0.f);
    float dsum = 0.f;
    const float4* x4 = (const float4*)x;
    int j = beg;

    // 8-wide batches: 8 independent x-row gathers in flight per warp
    for (; j + 8 <= end; j += 8) {
        int   s0 = g_esrc[j+0], s1 = g_esrc[j+1], s2 = g_esrc[j+2], s3 = g_esrc[j+3];
        int   s4 = g_esrc[j+4], s5 = g_esrc[j+5], s6 = g_esrc[j+6], s7 = g_esrc[j+7];
        float w0 = g_ewt[j+0], w1 = g_ewt[j+1], w2 = g_ewt[j+2], w3 = g_ewt[j+3];
        float w4 = g_ewt[j+4], w5 = g_ewt[j+5], w6 = g_ewt[j+6], w7 = g_ewt[j+7];
        float4 v0 = x4[(size_t)s0 * 32 + lane];
        float4 v1 = x4[(size_t)s1 * 32 + lane];
        float4 v2 = x4[(size_t)s2 * 32 + lane];
        float4 v3 = x4[(size_t)s3 * 32 + lane];
        float4 v4 = x4[(size_t)s4 * 32 + lane];
        float4 v5 = x4[(size_t)s5 * 32 + lane];
        float4 v6 = x4[(size_t)s6 * 32 + lane];
        float4 v7 = x4[(size_t)s7 * 32 + lane];
        acc.x = fmaf(w0, v0.x, fmaf(w1, v1.x, fmaf(w2, v2.x, fmaf(w3, v3.x, acc.x))));
        acc.y = fmaf(w0, v0.y, fmaf(w1, v1.y, fmaf(w2, v2.y, fmaf(w3, v3.y, acc.y))));
        acc.z = fmaf(w0, v0.z, fmaf(w1, v1.z, fmaf(w2, v2.z, fmaf(w3, v3.z, acc.z))));
        acc.w = fmaf(w0, v0.w, fmaf(w1, v1.w, fmaf(w2, v2.w, fmaf(w3, v3.w, acc.w))));
        acc.x = fmaf(w4, v4.x, fmaf(w5, v5.x, fmaf(w6, v6.x, fmaf(w7, v7.x, acc.x))));
        acc.y = fmaf(w4, v4.y, fmaf(w5, v5.y, fmaf(w6, v6.y, fmaf(w7, v7.y, acc.y))));
        acc.z = fmaf(w4, v4.z, fmaf(w5, v5.z, fmaf(w6, v6.z, fmaf(w7, v7.z, acc.z))));
        acc.w = fmaf(w4, v4.w, fmaf(w5, v5.w, fmaf(w6, v6.w, fmaf(w7, v7.w, acc.w))));
        dsum += (w0 + w1 + w2 + w3) + (w4 + w5 + w6 + w7);
    }
    // 4-wide batch
    if (j + 4 <= end) {
        int   s0 = g_esrc[j+0], s1 = g_esrc[j+1], s2 = g_esrc[j+2], s3 = g_esrc[j+3];
        float w0 = g_ewt[j+0], w1 = g_ewt[j+1], w2 = g_ewt[j+2], w3 = g_ewt[j+3];
        float4 v0 = x4[(size_t)s0 * 32 + lane];
        float4 v1 = x4[(size_t)s1 * 32 + lane];
        float4 v2 = x4[(size_t)s2 * 32 + lane];
        float4 v3 = x4[(size_t)s3 * 32 + lane];
        acc.x = fmaf(w0, v0.x, fmaf(w1, v1.x, fmaf(w2, v2.x, fmaf(w3, v3.x, acc.x))));
        acc.y = fmaf(w0, v0.y, fmaf(w1, v1.y, fmaf(w2, v2.y, fmaf(w3, v3.y, acc.y))));
        acc.z = fmaf(w0, v0.z, fmaf(w1, v1.z, fmaf(w2, v2.z, fmaf(w3, v3.z, acc.z))));
        acc.w = fmaf(w0, v0.w, fmaf(w1, v1.w, fmaf(w2, v2.w, fmaf(w3, v3.w, acc.w))));
        dsum += (w0 + w1) + (w2 + w3);
        j += 4;
    }
    // scalar tail
    for (; j < end; ++j) {
        int s = g_esrc[j];
        float wk = g_ewt[j];
        float4 v = x4[(size_t)s * 32 + lane];
        acc.x = fmaf(wk, v.x, acc.x);
        acc.y = fmaf(wk, v.y, acc.y);
        acc.z = fmaf(wk, v.z, acc.z);
        acc.w = fmaf(wk, v.w, acc.w);
        dsum += wk;
    }

    float ss = acc.x * acc.x + acc.y * acc.y + acc.z * acc.z + acc.w * acc.w;
    #pragma unroll
    for (int off = 16; off; off >>= 1)
        ss += __shfl_xor_sync(0xffffffffu, ss, off);
    float inv = (ss > 0.f) ? 1.0f / (sqrtf(ss) + dsum * 1e-9f) : 0.f;
    g_agg4[(size_t)gw * 32 + lane] =
        make_float4(inv * acc.x, inv * acc.y, inv * acc.z, inv * acc.w);
}

// ---------------------------------------------------------------------------
// HMMA fused dual GEMM (validated R13): hi/lo split + ldmatrix.trans
// ---------------------------------------------------------------------------
#define BLK_ROWS 128
#define RS 136
#define MATB 34816
#define CSTRIDE 132

#define OFF_XH 0
#define OFF_XL (MATB)
#define OFF_AH (2 * MATB)
#define OFF_AL (3 * MATB)
#define OFF_WH (4 * MATB)
#define OFF_WL (5 * MATB)
#define OFF_PAR (6 * MATB)
#define SMEM_TOTAL (OFF_PAR + 2048)

__device__ __forceinline__ void mma16816(float* d,
                                         unsigned a0, unsigned a1,
                                         unsigned a2, unsigned a3,
                                         unsigned b0, unsigned b1) {
    asm volatile(
        "mma.sync.aligned.m16n8k16.row.col.f32.bf16.bf16.f32 "
        "{%0,%1,%2,%3}, {%4,%5,%6,%7}, {%8,%9}, {%0,%1,%2,%3};"
        : "+f"(d[0]), "+f"(d[1]), "+f"(d[2]), "+f"(d[3])
        : "r"(a0), "r"(a1), "r"(a2), "r"(a3), "r"(b0), "r"(b1));
}

__device__ __forceinline__ void ldsm4(unsigned& r0, unsigned& r1,
                                      unsigned& r2, unsigned& r3,
                                      unsigned addr) {
    asm volatile("ldmatrix.sync.aligned.m8n8.x4.shared.b16 {%0,%1,%2,%3}, [%4];"
                 : "=r"(r0), "=r"(r1), "=r"(r2), "=r"(r3) : "r"(addr));
}

__device__ __forceinline__ void ldsm4t(unsigned& r0, unsigned& r1,
                                       unsigned& r2, unsigned& r3,
                                       unsigned addr) {
    asm volatile("ldmatrix.sync.aligned.m8n8.x4.trans.shared.b16 {%0,%1,%2,%3}, [%4];"
                 : "=r"(r0), "=r"(r1), "=r"(r2), "=r"(r3) : "r"(addr));
}

__device__ __forceinline__ unsigned pack2(float a, float b) {
    __nv_bfloat162 t = __floats2bfloat162_rn(a, b);
    return *(unsigned*)&t;
}

__device__ __forceinline__ void split4(float4 v, uint2& hw, uint2& lw) {
    __nv_bfloat16 h0 = __float2bfloat16(v.x), h1 = __float2bfloat16(v.y);
    __nv_bfloat16 h2 = __float2bfloat16(v.z), h3 = __float2bfloat16(v.w);
    hw.x = ((unsigned)*(unsigned short*)&h1 << 16) | *(unsigned short*)&h0;
    hw.y = ((unsigned)*(unsigned short*)&h3 << 16) | *(unsigned short*)&h2;
    lw.x = pack2(v.x - __bfloat162float(h0), v.y - __bfloat162float(h1));
    lw.y = pack2(v.z - __bfloat162float(h2), v.w - __bfloat162float(h3));
}

__device__ __forceinline__ void subpass(unsigned a_smem, unsigned w_smem,
                                        int a_off, int b_off,
                                        float* acc) {
    #pragma unroll
    for (int ks = 0; ks < 8; ++ks) {
        unsigned a0, a1, a2, a3;
        ldsm4(a0, a1, a2, a3, a_smem + (unsigned)(a_off + ks * 16) * 2);
        #pragma unroll
        for (int p = 0; p < 4; ++p) {
            unsigned s0, s1, s2, s3;
            ldsm4t(s0, s1, s2, s3,
                   w_smem + (unsigned)(b_off + ks * 16 * RS + p * 16) * 2);
            mma16816(&acc[(2 * p) * 4], a0, a1, a2, a3, s0, s1);
            mma16816(&acc[(2 * p + 1) * 4], a0, a1, a2, a3, s2, s3);
        }
    }
}

__global__ __launch_bounds__(512, 1)
void k_fused(const float* __restrict__ x,
             const float* __restrict__ Wself, const float* __restrict__ bself,
             const float* __restrict__ Wnb, const float* __restrict__ bnb,
             const float* __restrict__ gamma, const float* __restrict__ beta,
             float* __restrict__ out, int N) {
    extern __shared__ char smem[];
    __nv_bfloat16* XH = (__nv_bfloat16*)(smem + OFF_XH);
    __nv_bfloat16* XL = (__nv_bfloat16*)(smem + OFF_XL);
    __nv_bfloat16* AH = (__nv_bfloat16*)(smem + OFF_AH);
    __nv_bfloat16* AL = (__nv_bfloat16*)(smem + OFF_AL);
    __nv_bfloat16* WH = (__nv_bfloat16*)(smem + OFF_WH);
    __nv_bfloat16* WL = (__nv_bfloat16*)(smem + OFF_WL);
    float* sb   = (float*)(smem + OFF_PAR);
    float* snb  = (float*)(smem + OFF_PAR + 512);
    float* sg   = (float*)(smem + OFF_PAR + 1024);
    float* sbt  = (float*)(smem + OFF_PAR + 1536);

    int tid = threadIdx.x;
    int wid = tid >> 5, lane = tid & 31;
    int base = blockIdx.x * BLK_ROWS;
    const float* aggf = (const float*)g_agg4;

    if (tid < 128) {
        sb[tid] = bself[tid];
        snb[tid] = bnb[tid];
        sg[tid] = gamma[tid];
        sbt[tid] = beta[tid];
    }

    #pragma unroll
    for (int it = 0; it < 8; ++it) {
        int idx = tid + it * 512;
        int row = idx >> 5, c4 = idx & 31;
        int node = base + row; if (node >= N) node = N - 1;
        uint2 hw, lw;

        float4 v = ((const float4*)x)[(size_t)node * 32 + c4];
        split4(v, hw, lw);
        *(uint2*)(XH + row * RS + c4 * 4) = hw;
        *(uint2*)(XL + row * RS + c4 * 4) = lw;

        float4 a = ((const float4*)aggf)[(size_t)node * 32 + c4];
        split4(a, hw, lw);
        *(uint2*)(AH + row * RS + c4 * 4) = hw;
        *(uint2*)(AL + row * RS + c4 * 4) = lw;

        float4 w = ((const float4*)Wself)[row * 32 + c4];
        split4(w, hw, lw);
        *(uint2*)(WH + row * RS + c4 * 4) = hw;
        *(uint2*)(WL + row * RS + c4 * 4) = lw;
    }
    __syncthreads();

    int warp_m = wid >> 1, warp_n = wid & 1;
    int m0 = warp_m * 16;
    int q = lane >> 3, lr = lane & 7;
    int a_off = (m0 + (q & 1) * 8 + lr) * RS + (q >> 1) * 8;
    int b_off = (lane & 15) * RS + warp_n * 64 + (lane >> 4) * 8;

    unsigned xh_s = (unsigned)__cvta_generic_to_shared(XH);
    unsigned xl_s = (unsigned)__cvta_generic_to_shared(XL);
    unsigned ah_s = (unsigned)__cvta_generic_to_shared(AH);
    unsigned al_s = (unsigned)__cvta_generic_to_shared(AL);
    unsigned wh_s = (unsigned)__cvta_generic_to_shared(WH);
    unsigned wl_s = (unsigned)__cvta_generic_to_shared(WL);

    float acc[32];
    #pragma unroll
    for (int i = 0; i < 32; ++i) acc[i] = 0.f;

    subpass(xh_s, wh_s, a_off, b_off, acc);
    subpass(xl_s, wh_s, a_off, b_off, acc);
    subpass(xh_s, wl_s, a_off, b_off, acc);
    __syncthreads();

    #pragma unroll
    for (int it = 0; it < 8; ++it) {
        int idx = tid + it * 512;
        int k = idx >> 5, c4 = idx & 31;
        float4 w = ((const float4*)Wnb)[k * 32 + c4];
        uint2 hw, lw;
        split4(w, hw, lw);
        *(uint2*)(WH + k * RS + c4 * 4) = hw;
        *(uint2*)(WL + k * RS + c4 * 4) = lw;
    }
    __syncthreads();

    subpass(ah_s, wh_s, a_off, b_off, acc);
    subpass(al_s, wh_s, a_off, b_off, acc);
    subpass(ah_s, wl_s, a_off, b_off, acc);

    float* Cb = (float*)smem;
    {
        int row0 = m0 + (lane >> 2);
        int row1 = row0 + 8;
        int tr = lane & 3;
        #pragma unroll
        for (int nt = 0; nt < 8; ++nt) {
            int col = warp_n * 64 + nt * 8 + 2 * tr;
            float b0 = sb[col] + snb[col];
            float b1 = sb[col + 1] + snb[col + 1];
            const float* d = &acc[nt * 4];
            float2 c0, c1;
            c0.x = 0.5f * (d[0] + b0);
            c0.y = 0.5f * (d[1] + b1);
            c1.x = 0.5f * (d[2] + b0);
            c1.y = 0.5f * (d[3] + b1);
            *(float2*)(Cb + row0 * CSTRIDE + col) = c0;
            *(float2*)(Cb + row1 * CSTRIDE + col) = c1;
        }
    }
    __syncthreads();

    float4 gm = ((const float4*)sg)[lane];
    float4 bt4 = ((const float4*)sbt)[lane];
    #pragma unroll
    for (int i = 0; i < 8; ++i) {
        int r = wid * 8 + i;
        int node = base + r;
        if (node >= N) continue;
        float4 c = *(const float4*)(Cb + r * CSTRIDE + lane * 4);
        float s1 = c.x + c.y + c.z + c.w;
        float s2 = c.x * c.x + c.y * c.y + c.z * c.z + c.w * c.w;
        #pragma unroll
        for (int off = 16; off; off >>= 1) {
            s1 += __shfl_xor_sync(0xffffffffu, s1, off);
            s2 += __shfl_xor_sync(0xffffffffu, s2, off);
        }
        float d = sqrtf(s2) + 1e-9f;
        float invd = 1.0f / d;
        float mean = s1 * invd * (1.0f / 128.0f);
        float e2 = s2 * invd * invd * (1.0f / 128.0f);
        float var = e2 - mean * mean;
        float isd = rsqrtf(var + 1e-5f);
        float4 o;
        o.x = (c.x * invd - mean) * isd * gm.x + bt4.x;
        o.y = (c.y * invd - mean) * isd * gm.y + bt4.y;
        o.z = (c.z * invd - mean) * isd * gm.z + bt4.z;
        o.w = (c.w * invd - mean) * isd * gm.w + bt4.w;
        ((float4*)out)[(size_t)node * 32 + lane] = o;
    }
}

// ---------------------------------------------------------------------------
extern "C" void kernel_launch(void* const* d_in, const int* in_sizes, int n_in,
                              void* d_out, int out_size) {
    const float* x     = (const float*)d_in[0];
    const int*   ei    = (const int*)d_in[1];
    const float* ew    = (const float*)d_in[2];
    const float* Wself = (const float*)d_in[3];
    const float* bself = (const float*)d_in[4];
    const float* Wnb   = (const float*)d_in[5];
    const float* bnb   = (const float*)d_in[6];
    const float* gamma = (const float*)d_in[7];
    const float* beta  = (const float*)d_in[8];
    float* out         = (float*)d_out;

    int N = in_sizes[0] / F;
    int E = in_sizes[2];

    k_zero_cnt<<<(N + 255) / 256, 256>>>(N);
    int be = (E + 255) / 256;
    k_count<<<be, 256>>>(ei, E, N);
    k_scan<<<1, SCAN_T>>>(N);
    k_fill<<<be, 256>>>(ei, ew, E, N);
    int bw = (N * 32 + 255) / 256;
    k_aggregate<<<bw, 256>>>(x, N);

    cudaFuncSetAttribute(k_fused, cudaFuncAttributeMaxDynamicSharedMemorySize,
                         SMEM_TOTAL);
    int b3 = (N + BLK_ROWS - 1) / BLK_ROWS;
    k_fused<<<b3, 512, SMEM_TOTAL>>>(x, Wself, bself, Wnb, bnb, gamma, beta,
                                     out, N);
}

// round 16
// speedup vs baseline: 1.2093x; 1.2093x over previous
#include <cuda_runtime.h>
#include <cuda_bf16.h>

#define F 128
#define CAP_N 51200
#define CAP_E 650000

__device__ float4 g_agg4[(size_t)CAP_N * (F / 4)];  // raw weighted sums S
__device__ float  g_ew[CAP_E];                      // exp(edge_weight)

// ---------------------------------------------------------------------------
// K0: zero agg scratch
// ---------------------------------------------------------------------------
__global__ void k_zero(int N) {
    int i = blockIdx.x * blockDim.x + threadIdx.x;
    int total4 = N * (F / 4);
    if (i < total4)
        g_agg4[i] = make_float4(0.f, 0.f, 0.f, 0.f);
}

// ---------------------------------------------------------------------------
// K1: ew[e] = exp(w[e])   (no atomics — denominator is algebraically folded
// into the L2 norm and its 1e-9-scaled residual is ~1e-9 relative: dropped)
// ---------------------------------------------------------------------------
__global__ void k_exp(const float* __restrict__ w, int E) {
    int e = blockIdx.x * blockDim.x + threadIdx.x;
    if (e < E) g_ew[e] = expf(w[e]);
}

// ---------------------------------------------------------------------------
// K2: one warp per edge; S[t] += ew * x[src]   (vector REDG, no denom read)
// ---------------------------------------------------------------------------
__global__ void k_scatter(const float* __restrict__ x,
                          const int* __restrict__ ei, int E, int N) {
    int gid = blockIdx.x * blockDim.x + threadIdx.x;
    int e = gid >> 5;
    int lane = gid & 31;
    if (e >= E) return;
    int s = ei[e];
    int t = ei[E + e];
    if ((unsigned)s >= (unsigned)N || (unsigned)t >= (unsigned)N) return;
    float ew = g_ew[e];
    float4 xv = reinterpret_cast<const float4*>(x)[(size_t)s * 32 + lane];
    float4 v = make_float4(ew * xv.x, ew * xv.y, ew * xv.z, ew * xv.w);
    atomicAdd(&g_agg4[(size_t)t * 32 + lane], v);
}

// ---------------------------------------------------------------------------
// HMMA fused dual GEMM (R11, measured 88.4us): hi/lo split + ldmatrix.trans
// ---------------------------------------------------------------------------
#define BLK_ROWS 128
#define RS 136
#define MATB 34816
#define CSTRIDE 132

#define OFF_XH 0
#define OFF_XL (MATB)
#define OFF_AH (2 * MATB)
#define OFF_AL (3 * MATB)
#define OFF_WH (4 * MATB)
#define OFF_WL (5 * MATB)
#define OFF_PAR (6 * MATB)
#define SMEM_TOTAL (OFF_PAR + 2560)

__device__ __forceinline__ void mma16816(float* d,
                                         unsigned a0, unsigned a1,
                                         unsigned a2, unsigned a3,
                                         unsigned b0, unsigned b1) {
    asm volatile(
        "mma.sync.aligned.m16n8k16.row.col.f32.bf16.bf16.f32 "
        "{%0,%1,%2,%3}, {%4,%5,%6,%7}, {%8,%9}, {%0,%1,%2,%3};"
        : "+f"(d[0]), "+f"(d[1]), "+f"(d[2]), "+f"(d[3])
        : "r"(a0), "r"(a1), "r"(a2), "r"(a3), "r"(b0), "r"(b1));
}

__device__ __forceinline__ void ldsm4(unsigned& r0, unsigned& r1,
                                      unsigned& r2, unsigned& r3,
                                      unsigned addr) {
    asm volatile("ldmatrix.sync.aligned.m8n8.x4.shared.b16 {%0,%1,%2,%3}, [%4];"
                 : "=r"(r0), "=r"(r1), "=r"(r2), "=r"(r3) : "r"(addr));
}

__device__ __forceinline__ void ldsm4t(unsigned& r0, unsigned& r1,
                                       unsigned& r2, unsigned& r3,
                                       unsigned addr) {
    asm volatile("ldmatrix.sync.aligned.m8n8.x4.trans.shared.b16 {%0,%1,%2,%3}, [%4];"
                 : "=r"(r0), "=r"(r1), "=r"(r2), "=r"(r3) : "r"(addr));
}

__device__ __forceinline__ unsigned pack2(float a, float b) {
    __nv_bfloat162 t = __floats2bfloat162_rn(a, b);
    return *(unsigned*)&t;
}

__device__ __forceinline__ void split4(float4 v, uint2& hw, uint2& lw) {
    __nv_bfloat16 h0 = __float2bfloat16(v.x), h1 = __float2bfloat16(v.y);
    __nv_bfloat16 h2 = __float2bfloat16(v.z), h3 = __float2bfloat16(v.w);
    hw.x = ((unsigned)*(unsigned short*)&h1 << 16) | *(unsigned short*)&h0;
    hw.y = ((unsigned)*(unsigned short*)&h3 << 16) | *(unsigned short*)&h2;
    lw.x = pack2(v.x - __bfloat162float(h0), v.y - __bfloat162float(h1));
    lw.y = pack2(v.z - __bfloat162float(h2), v.w - __bfloat162float(h3));
}

__device__ __forceinline__ void subpass(unsigned a_smem, unsigned w_smem,
                                        int a_off, int b_off,
                                        float* acc) {
    #pragma unroll
    for (int ks = 0; ks < 8; ++ks) {
        unsigned a0, a1, a2, a3;
        ldsm4(a0, a1, a2, a3, a_smem + (unsigned)(a_off + ks * 16) * 2);
        #pragma unroll
        for (int p = 0; p < 4; ++p) {
            unsigned s0, s1, s2, s3;
            ldsm4t(s0, s1, s2, s3,
                   w_smem + (unsigned)(b_off + ks * 16 * RS + p * 16) * 2);
            mma16816(&acc[(2 * p) * 4], a0, a1, a2, a3, s0, s1);
            mma16816(&acc[(2 * p + 1) * 4], a0, a1, a2, a3, s2, s3);
        }
    }
}

__global__ __launch_bounds__(512, 1)
void k_fused(const float* __restrict__ x,
             const float* __restrict__ Wself, const float* __restrict__ bself,
             const float* __restrict__ Wnb, const float* __restrict__ bnb,
             const float* __restrict__ gamma, const float* __restrict__ beta,
             float* __restrict__ out, int N) {
    extern __shared__ char smem[];
    __nv_bfloat16* XH = (__nv_bfloat16*)(smem + OFF_XH);
    __nv_bfloat16* XL = (__nv_bfloat16*)(smem + OFF_XL);
    __nv_bfloat16* AH = (__nv_bfloat16*)(smem + OFF_AH);
    __nv_bfloat16* AL = (__nv_bfloat16*)(smem + OFF_AL);
    __nv_bfloat16* WH = (__nv_bfloat16*)(smem + OFF_WH);
    __nv_bfloat16* WL = (__nv_bfloat16*)(smem + OFF_WL);
    float* sb   = (float*)(smem + OFF_PAR);
    float* snb  = (float*)(smem + OFF_PAR + 512);
    float* sg   = (float*)(smem + OFF_PAR + 1024);
    float* sbt  = (float*)(smem + OFF_PAR + 1536);
    float* sinv = (float*)(smem + OFF_PAR + 2048);

    int tid = threadIdx.x;
    int wid = tid >> 5, lane = tid & 31;
    int base = blockIdx.x * BLK_ROWS;
    const float* aggf = (const float*)g_agg4;

    // ---- phase 0: agg row inverse norms + params ----
    #pragma unroll
    for (int i = 0; i < 8; ++i) {
        int r = wid * 8 + i;
        int node = base + r; if (node >= N) node = N - 1;
        float4 a = g_agg4[(size_t)node * 32 + lane];
        float ss = a.x * a.x + a.y * a.y + a.z * a.z + a.w * a.w;
        #pragma unroll
        for (int off = 16; off; off >>= 1)
            ss += __shfl_xor_sync(0xffffffffu, ss, off);
        if (lane == 0) sinv[r] = 1.0f / (sqrtf(ss) + 1e-9f);
    }
    if (tid < 128) {
        sb[tid] = bself[tid];
        snb[tid] = bnb[tid];
        sg[tid] = gamma[tid];
        sbt[tid] = beta[tid];
    }
    __syncthreads();

    // ---- stage X, AG = inv*S (both [m][k]) and W_self ([k][n]) ----
    #pragma unroll
    for (int it = 0; it < 8; ++it) {
        int idx = tid + it * 512;
        int row = idx >> 5, c4 = idx & 31;
        int node = base + row; if (node >= N) node = N - 1;
        uint2 hw, lw;

        float4 v = ((const float4*)x)[(size_t)node * 32 + c4];
        split4(v, hw, lw);
        *(uint2*)(XH + row * RS + c4 * 4) = hw;
        *(uint2*)(XL + row * RS + c4 * 4) = lw;

        float iv = sinv[row];
        float4 a = ((const float4*)aggf)[(size_t)node * 32 + c4];
        a.x *= iv; a.y *= iv; a.z *= iv; a.w *= iv;
        split4(a, hw, lw);
        *(uint2*)(AH + row * RS + c4 * 4) = hw;
        *(uint2*)(AL + row * RS + c4 * 4) = lw;

        float4 w = ((const float4*)Wself)[row * 32 + c4];
        split4(w, hw, lw);
        *(uint2*)(WH + row * RS + c4 * 4) = hw;
        *(uint2*)(WL + row * RS + c4 * 4) = lw;
    }
    __syncthreads();

    int warp_m = wid >> 1, warp_n = wid & 1;
    int m0 = warp_m * 16;
    int q = lane >> 3, lr = lane & 7;
    int a_off = (m0 + (q & 1) * 8 + lr) * RS + (q >> 1) * 8;
    int b_off = (lane & 15) * RS + warp_n * 64 + (lane >> 4) * 8;

    unsigned xh_s = (unsigned)__cvta_generic_to_shared(XH);
    unsigned xl_s = (unsigned)__cvta_generic_to_shared(XL);
    unsigned ah_s = (unsigned)__cvta_generic_to_shared(AH);
    unsigned al_s = (unsigned)__cvta_generic_to_shared(AL);
    unsigned wh_s = (unsigned)__cvta_generic_to_shared(WH);
    unsigned wl_s = (unsigned)__cvta_generic_to_shared(WL);

    float acc[32];
    #pragma unroll
    for (int i = 0; i < 32; ++i) acc[i] = 0.f;

    subpass(xh_s, wh_s, a_off, b_off, acc);
    subpass(xl_s, wh_s, a_off, b_off, acc);
    subpass(xh_s, wl_s, a_off, b_off, acc);
    __syncthreads();

    #pragma unroll
    for (int it = 0; it < 8; ++it) {
        int idx = tid + it * 512;
        int k = idx >> 5, c4 = idx & 31;
        float4 w = ((const float4*)Wnb)[k * 32 + c4];
        uint2 hw, lw;
        split4(w, hw, lw);
        *(uint2*)(WH + k * RS + c4 * 4) = hw;
        *(uint2*)(WL + k * RS + c4 * 4) = lw;
    }
    __syncthreads();

    subpass(ah_s, wh_s, a_off, b_off, acc);
    subpass(al_s, wh_s, a_off, b_off, acc);
    subpass(ah_s, wl_s, a_off, b_off, acc);

    float* Cb = (float*)smem;
    {
        int row0 = m0 + (lane >> 2);
        int row1 = row0 + 8;
        int tr = lane & 3;
        #pragma unroll
        for (int nt = 0; nt < 8; ++nt) {
            int col = warp_n * 64 + nt * 8 + 2 * tr;
            float b0 = sb[col] + snb[col];
            float b1 = sb[col + 1] + snb[col + 1];
            const float* d = &acc[nt * 4];
            float2 c0, c1;
            c0.x = 0.5f * (d[0] + b0);
            c0.y = 0.5f * (d[1] + b1);
            c1.x = 0.5f * (d[2] + b0);
            c1.y = 0.5f * (d[3] + b1);
            *(float2*)(Cb + row0 * CSTRIDE + col) = c0;
            *(float2*)(Cb + row1 * CSTRIDE + col) = c1;
        }
    }
    __syncthreads();

    float4 gm = ((const float4*)sg)[lane];
    float4 bt4 = ((const float4*)sbt)[lane];
    #pragma unroll
    for (int i = 0; i < 8; ++i) {
        int r = wid * 8 + i;
        int node = base + r;
        if (node >= N) continue;
        float4 c = *(const float4*)(Cb + r * CSTRIDE + lane * 4);
        float s1 = c.x + c.y + c.z + c.w;
        float s2 = c.x * c.x + c.y * c.y + c.z * c.z + c.w * c.w;
        #pragma unroll
        for (int off = 16; off; off >>= 1) {
            s1 += __shfl_xor_sync(0xffffffffu, s1, off);
            s2 += __shfl_xor_sync(0xffffffffu, s2, off);
        }
        float d = sqrtf(s2) + 1e-9f;
        float invd = 1.0f / d;
        float mean = s1 * invd * (1.0f / 128.0f);
        float e2 = s2 * invd * invd * (1.0f / 128.0f);
        float var = e2 - mean * mean;
        float isd = rsqrtf(var + 1e-5f);
        float4 o;
        o.x = (c.x * invd - mean) * isd * gm.x + bt4.x;
        o.y = (c.y * invd - mean) * isd * gm.y + bt4.y;
        o.z = (c.z * invd - mean) * isd * gm.z + bt4.z;
        o.w = (c.w * invd - mean) * isd * gm.w + bt4.w;
        ((float4*)out)[(size_t)node * 32 + lane] = o;
    }
}

// ---------------------------------------------------------------------------
extern "C" void kernel_launch(void* const* d_in, const int* in_sizes, int n_in,
                              void* d_out, int out_size) {
    const float* x     = (const float*)d_in[0];
    const int*   ei    = (const int*)d_in[1];
    const float* ew    = (const float*)d_in[2];
    const float* Wself = (const float*)d_in[3];
    const float* bself = (const float*)d_in[4];
    const float* Wnb   = (const float*)d_in[5];
    const float* bnb   = (const float*)d_in[6];
    const float* gamma = (const float*)d_in[7];
    const float* beta  = (const float*)d_in[8];
    float* out         = (float*)d_out;

    int N = in_sizes[0] / F;
    int E = in_sizes[2];

    int zt = N * (F / 4);
    k_zero<<<(zt + 255) / 256, 256>>>(N);

    k_exp<<<(E + 255) / 256, 256>>>(ew, E);

    long long tot = (long long)E * 32;
    int b2 = (int)((tot + 255) / 256);
    k_scatter<<<b2, 256>>>(x, ei, E, N);

    cudaFuncSetAttribute(k_fused, cudaFuncAttributeMaxDynamicSharedMemorySize,
                         SMEM_TOTAL);
    int b3 = (N + BLK_ROWS - 1) / BLK_ROWS;
    k_fused<<<b3, 512, SMEM_TOTAL>>>(x, Wself, bself, Wnb, bnb, gamma, beta,
                                     out, N);
}